// round 2
// baseline (speedup 1.0000x reference)
#include <cuda_runtime.h>
#include <math.h>
#include <stdint.h>

#define HDIM 1024
#define SDIM 512
#define NB   160
#define NTOPK 5
#define NSTEPS 4
#define NBASE 32
#define NEGV -10000000000.0f

// ---------------- scratch (device globals; no allocation allowed) ----------------
__device__ __align__(16) float g_gi[NB * 3 * HDIM];
__device__ __align__(16) float g_gh[NB * 3 * HDIM];
__device__ __align__(16) float g_hnew[NB * HDIM];
__device__ __align__(16) float g_q[NB * HDIM];
__device__ float g_hb1[NB];
__device__ __align__(16) float g_attnout[NB * SDIM];
__device__ float g_mpart[NB * 2];
__device__ float g_zpart[NB * 2];
__device__ __align__(16) float g_c0part[NB * 2 * HDIM];
__device__ float g_m[NB];
__device__ float g_z[NB];
__device__ __align__(16) float g_c0[NB * HDIM];
__device__ float g_ls[NB * NTOPK];
__device__ int   g_sent[NB * NTOPK];
__device__ int   g_sflat[NB];
__device__ int   g_newsent[NB];
__device__ __align__(16) float g_ctx[NB * HDIM];
__device__ __align__(16) float g_cat[NB * 2 * HDIM];

// ---------------- f32x2 packed-FMA helpers (sm_100 fp32 2x path) ----------------
__device__ __forceinline__ unsigned long long f32x2_dup(float x) {
    unsigned long long r;
    asm("mov.b64 %0, {%1, %1};" : "=l"(r) : "f"(x));
    return r;
}
__device__ __forceinline__ void ffma2(unsigned long long& d, unsigned long long a, unsigned long long b) {
    asm("fma.rn.f32x2 %0, %1, %2, %0;" : "+l"(d) : "l"(a), "l"(b));
}
__device__ __forceinline__ float2 f32x2_unpack(unsigned long long v) {
    float2 r;
    asm("mov.b64 {%0, %1}, %2;" : "=f"(r.x), "=f"(r.y) : "l"(v));
    return r;
}

// ---------------- generic fp32 GEMM tile: C[M,N] = A[M,K] * op(B) + bias ----------------
// TRANSB=true : B is (N,K) row-major (weight matrices, output features as rows)
// TRANSB=false: B is (K,N) row-major
// rowmap (optional): A row gather indices.
// BM=64, BN=128, BK=16, 256 threads, thread tile 8x4 via f32x2 row-pairs.
template <bool TRANSB>
__device__ __forceinline__ void gemm_tile(
    const float* __restrict__ A, const float* __restrict__ B,
    const float* __restrict__ bias, float* __restrict__ C,
    int M, int N, int K, const int* __restrict__ rowmap,
    int bx, int by)
{
    __shared__ __align__(16) float As[16][64];
    __shared__ __align__(16) float Bs[16][128];

    const int tid = threadIdx.x;
    const int tx = tid & 31;        // 0..31 -> cols tx*4
    const int ty = tid >> 5;        // 0..7  -> rows ty*8
    const int m0 = by * 64, n0 = bx * 128;

    unsigned long long acc[4][4];
#pragma unroll
    for (int i = 0; i < 4; i++)
#pragma unroll
        for (int j = 0; j < 4; j++) acc[i][j] = 0ull;

    // A load mapping: one float4 per thread per tile
    const int am  = tid >> 2;          // 0..63
    const int akq = (tid & 3) * 4;     // 0,4,8,12
    const int arow = m0 + am;
    int arid = -1;
    if (arow < M) arid = rowmap ? rowmap[arow] : arow;

    for (int k0 = 0; k0 < K; k0 += 16) {
        float4 av = make_float4(0.f, 0.f, 0.f, 0.f);
        if (arid >= 0)
            av = *reinterpret_cast<const float4*>(A + (size_t)arid * K + k0 + akq);
        As[akq + 0][am] = av.x; As[akq + 1][am] = av.y;
        As[akq + 2][am] = av.z; As[akq + 3][am] = av.w;

        if (TRANSB) {
            const int bn  = tid >> 1;         // 0..127
            const int bkq = (tid & 1) * 8;    // 0 or 8
            const float* bp = B + (size_t)(n0 + bn) * K + k0 + bkq;
            float4 v0 = *reinterpret_cast<const float4*>(bp);
            float4 v1 = *reinterpret_cast<const float4*>(bp + 4);
            Bs[bkq + 0][bn] = v0.x; Bs[bkq + 1][bn] = v0.y;
            Bs[bkq + 2][bn] = v0.z; Bs[bkq + 3][bn] = v0.w;
            Bs[bkq + 4][bn] = v1.x; Bs[bkq + 5][bn] = v1.y;
            Bs[bkq + 6][bn] = v1.z; Bs[bkq + 7][bn] = v1.w;
        } else {
#pragma unroll
            for (int r = 0; r < 2; r++) {
                int idx = tid + r * 256;
                int bk = idx >> 5, bnq = (idx & 31) * 4;
                float4 v = *reinterpret_cast<const float4*>(B + (size_t)(k0 + bk) * N + n0 + bnq);
                *reinterpret_cast<float4*>(&Bs[bk][bnq]) = v;
            }
        }
        __syncthreads();

#pragma unroll
        for (int k = 0; k < 16; k++) {
            const unsigned long long* Ar =
                reinterpret_cast<const unsigned long long*>(&As[k][0]);
            unsigned long long a0 = Ar[ty * 4 + 0];
            unsigned long long a1 = Ar[ty * 4 + 1];
            unsigned long long a2 = Ar[ty * 4 + 2];
            unsigned long long a3 = Ar[ty * 4 + 3];
            float4 bv = *reinterpret_cast<const float4*>(&Bs[k][tx * 4]);
            unsigned long long b0 = f32x2_dup(bv.x);
            unsigned long long b1 = f32x2_dup(bv.y);
            unsigned long long b2 = f32x2_dup(bv.z);
            unsigned long long b3 = f32x2_dup(bv.w);
            ffma2(acc[0][0], a0, b0); ffma2(acc[0][1], a0, b1);
            ffma2(acc[0][2], a0, b2); ffma2(acc[0][3], a0, b3);
            ffma2(acc[1][0], a1, b0); ffma2(acc[1][1], a1, b1);
            ffma2(acc[1][2], a1, b2); ffma2(acc[1][3], a1, b3);
            ffma2(acc[2][0], a2, b0); ffma2(acc[2][1], a2, b1);
            ffma2(acc[2][2], a2, b2); ffma2(acc[2][3], a2, b3);
            ffma2(acc[3][0], a3, b0); ffma2(acc[3][1], a3, b1);
            ffma2(acc[3][2], a3, b2); ffma2(acc[3][3], a3, b3);
        }
        __syncthreads();
    }

    const int cbase = n0 + tx * 4;
    float bx0 = 0.f, bx1 = 0.f, bx2 = 0.f, bx3 = 0.f;
    if (bias) { bx0 = bias[cbase]; bx1 = bias[cbase + 1]; bx2 = bias[cbase + 2]; bx3 = bias[cbase + 3]; }
#pragma unroll
    for (int ii = 0; ii < 4; ii++) {
        float2 u0 = f32x2_unpack(acc[ii][0]);
        float2 u1 = f32x2_unpack(acc[ii][1]);
        float2 u2 = f32x2_unpack(acc[ii][2]);
        float2 u3 = f32x2_unpack(acc[ii][3]);
        int r0 = m0 + ty * 8 + ii * 2;
        if (r0 < M) {
            float4 o = make_float4(u0.x + bx0, u1.x + bx1, u2.x + bx2, u3.x + bx3);
            *reinterpret_cast<float4*>(&C[(size_t)r0 * N + cbase]) = o;
        }
        if (r0 + 1 < M) {
            float4 o = make_float4(u0.y + bx0, u1.y + bx1, u2.y + bx2, u3.y + bx3);
            *reinterpret_cast<float4*>(&C[(size_t)(r0 + 1) * N + cbase]) = o;
        }
    }
}

// ---------------- GEMM kernel wrappers ----------------
__global__ void k_gru_gemm(const float* __restrict__ dec, const float* __restrict__ lasth,
                           const float* __restrict__ W_ih, const float* __restrict__ W_hh,
                           const float* __restrict__ b_ih, const float* __restrict__ b_hh)
{
    const float* A    = (blockIdx.z == 0) ? dec  : lasth;
    const float* B    = (blockIdx.z == 0) ? W_ih : W_hh;
    const float* bias = (blockIdx.z == 0) ? b_ih : b_hh;
    float* C          = (blockIdx.z == 0) ? g_gi : g_gh;
    gemm_tile<true>(A, B, bias, C, NB, 3 * HDIM, HDIM, nullptr, blockIdx.x, blockIdx.y);
}

__global__ void k_gemm_q(const float* __restrict__ W1)
{
    // q = h_new @ W1   (B is (K,N) row-major -> no transpose)
    gemm_tile<false>(g_hnew, W1, nullptr, g_q, NB, HDIM, HDIM, nullptr, blockIdx.x, blockIdx.y);
}

__global__ void k_gemm_ctx(const float* __restrict__ W2, const float* __restrict__ b2)
{
    // ctx[j] = W2 * c0[sflat[j]] + b2
    gemm_tile<true>(g_c0, W2, b2, g_ctx, NB, HDIM, HDIM, g_sflat, blockIdx.x, blockIdx.y);
}

__global__ void k_gemm_result(const float* __restrict__ W3, const float* __restrict__ b3,
                              float* __restrict__ out_result)
{
    gemm_tile<true>(g_cat, W3, b3, out_result, NB, HDIM, 2 * HDIM, nullptr, blockIdx.x, blockIdx.y);
}

// ---------------- GRU gates ----------------
__global__ void k_gates(const float* __restrict__ lasth)
{
    int b = blockIdx.x;
    for (int n = threadIdx.x; n < HDIM; n += blockDim.x) {
        float gir = g_gi[b * 3 * HDIM + n];
        float giz = g_gi[b * 3 * HDIM + HDIM + n];
        float gin = g_gi[b * 3 * HDIM + 2 * HDIM + n];
        float ghr = g_gh[b * 3 * HDIM + n];
        float ghz = g_gh[b * 3 * HDIM + HDIM + n];
        float ghn = g_gh[b * 3 * HDIM + 2 * HDIM + n];
        float r = 1.f / (1.f + __expf(-(gir + ghr)));
        float z = 1.f / (1.f + __expf(-(giz + ghz)));
        float nn = tanhf(gin + r * ghn);
        float hp = lasth[b * HDIM + n];
        g_hnew[b * HDIM + n] = (1.f - z) * nn + z * hp;
    }
}

// ---------------- hb1 = h_new . b1 ----------------
__global__ void k_hb1(const float* __restrict__ b1)
{
    int b = blockIdx.x;
    float s = 0.f;
    for (int n = threadIdx.x; n < HDIM; n += 256) s += g_hnew[b * HDIM + n] * b1[n];
    __shared__ float red[256];
    red[threadIdx.x] = s;
    __syncthreads();
    for (int off = 128; off > 0; off >>= 1) {
        if (threadIdx.x < off) red[threadIdx.x] += red[threadIdx.x + off];
        __syncthreads();
    }
    if (threadIdx.x == 0) g_hb1[b] = red[0];
}

// ---------------- fused attention: logits + online softmax + weighted-sum of enc ----------------
// grid (160, 2), 256 threads (8 warps), each warp handles 32 s-rows of its half.
__global__ void __launch_bounds__(256, 2) k_attn(const float* __restrict__ enc,
                                                 const float* __restrict__ mask)
{
    const int b = blockIdx.x;
    const int half = blockIdx.y;
    const int w = threadIdx.x >> 5, l = threadIdx.x & 31;

    const float4* q4 = reinterpret_cast<const float4*>(g_q + (size_t)b * HDIM);
    float4 qr[8];
#pragma unroll
    for (int j = 0; j < 8; j++) qr[j] = q4[l + 32 * j];
    const float hb1 = g_hb1[b];

    float4 acc[8];
#pragma unroll
    for (int j = 0; j < 8; j++) acc[j] = make_float4(0.f, 0.f, 0.f, 0.f);
    float m = -INFINITY, Z = 0.f;
    float mylogit = 0.f;

    const float4* encb = reinterpret_cast<const float4*>(enc + (size_t)b * SDIM * HDIM);
    const int srow0 = half * 256 + w * 32;

    for (int t = 0; t < 32; t++) {
        const int s = srow0 + t;
        const float4* rp = encb + (size_t)s * (HDIM / 4);
        float4 e[8];
        float d = 0.f;
#pragma unroll
        for (int j = 0; j < 8; j++) {
            e[j] = rp[l + 32 * j];
            d += e[j].x * qr[j].x + e[j].y * qr[j].y + e[j].z * qr[j].z + e[j].w * qr[j].w;
        }
#pragma unroll
        for (int off = 16; off; off >>= 1) d += __shfl_xor_sync(0xffffffffu, d, off);

        float logit = (d + hb1) * 0.03125f + mask[b * SDIM + s];
        if (t == l) mylogit = logit;

        float mn = fmaxf(m, logit);
        float corr = __expf(m - mn);
        float p = __expf(logit - mn);
        Z = Z * corr + p;
#pragma unroll
        for (int j = 0; j < 8; j++) {
            acc[j].x = acc[j].x * corr + p * e[j].x;
            acc[j].y = acc[j].y * corr + p * e[j].y;
            acc[j].z = acc[j].z * corr + p * e[j].z;
            acc[j].w = acc[j].w * corr + p * e[j].w;
        }
        m = mn;
    }
    g_attnout[b * SDIM + srow0 + l] = mylogit;

    __shared__ float sm[8], sz[8];
    __shared__ __align__(16) float c0s[8][HDIM];
    if (l == 0) sm[w] = m;
    __syncthreads();
    float M2 = sm[0];
#pragma unroll
    for (int i = 1; i < 8; i++) M2 = fmaxf(M2, sm[i]);
    float f = __expf(m - M2);
    float4* crow = reinterpret_cast<float4*>(&c0s[w][0]);
#pragma unroll
    for (int j = 0; j < 8; j++) {
        float4 v = acc[j];
        v.x *= f; v.y *= f; v.z *= f; v.w *= f;
        crow[l + 32 * j] = v;
    }
    if (l == 0) sz[w] = Z * f;
    __syncthreads();

    float Ztot = 0.f;
#pragma unroll
    for (int i = 0; i < 8; i++) Ztot += sz[i];
    for (int h = threadIdx.x; h < HDIM; h += 256) {
        float ssum = 0.f;
#pragma unroll
        for (int wi = 0; wi < 8; wi++) ssum += c0s[wi][h];
        g_c0part[((size_t)b * 2 + half) * HDIM + h] = ssum;
    }
    if (threadIdx.x == 0) {
        g_mpart[b * 2 + half] = M2;
        g_zpart[b * 2 + half] = Ztot;
    }
}

__global__ void k_attn_combine()
{
    int b = blockIdx.x;
    float m0 = g_mpart[b * 2], m1 = g_mpart[b * 2 + 1];
    float M2 = fmaxf(m0, m1);
    float f0 = __expf(m0 - M2), f1 = __expf(m1 - M2);
    // total normalizer (computed redundantly in every thread)
    float Zt = g_zpart[b * 2] * f0 + g_zpart[b * 2 + 1] * f1;
    float inv = 1.0f / Zt;
    if (threadIdx.x == 0) {
        g_m[b] = M2;
        g_z[b] = Zt;
    }
    for (int h = threadIdx.x; h < HDIM; h += blockDim.x)
        g_c0[b * HDIM + h] =
            (g_c0part[(size_t)(b * 2) * HDIM + h] * f0 +
             g_c0part[(size_t)(b * 2 + 1) * HDIM + h] * f1) * inv;   // <-- normalize by Z (bug fix)
}

// ---------------- per-row top-5 (max value, min index tie-break == jax top_k) ----------------
__global__ void k_topk(const float* __restrict__ ev)
{
    int b = blockIdx.x, l = threadIdx.x;
    float vals[16];
#pragma unroll
    for (int j = 0; j < 16; j++) vals[j] = g_attnout[b * SDIM + l + 32 * j];
    float lse = g_m[b] + logf(g_z[b]);
    float evb = ev[b];

    for (int r = 0; r < NTOPK; r++) {
        float bv = -INFINITY; int bj = 0;
#pragma unroll
        for (int j = 0; j < 16; j++) {
            if (vals[j] > bv) { bv = vals[j]; bj = j; }  // strict > keeps smallest s within lane
        }
        int bi = l + 32 * bj;
        if (bv == -INFINITY) bi = 0x7fffffff;
#pragma unroll
        for (int off = 16; off; off >>= 1) {
            float ov = __shfl_xor_sync(0xffffffffu, bv, off);
            int   oi = __shfl_xor_sync(0xffffffffu, bi, off);
            if (ov > bv || (ov == bv && oi < bi)) { bv = ov; bi = oi; }
        }
        if ((bi & 31) == l && (bi >> 5) < 16) vals[bi >> 5] = -INFINITY;
        if (l == 0) {
            g_ls[b * NTOPK + r] = lse - bv + evb;   // -log(alpha) + evidence
            g_sent[b * NTOPK + r] = bi;
        }
    }
}

// ---------------- beam select: 5 smallest of 25, stable (== argsort[:,:5]) ----------------
__global__ void k_beam(float* __restrict__ out_ev)
{
    int g = blockIdx.x, l = threadIdx.x;
    float v = (l < 25) ? g_ls[g * 25 + l] : INFINITY;
    for (int r = 0; r < NTOPK; r++) {
        float bv = v; int bi = l;
#pragma unroll
        for (int off = 16; off; off >>= 1) {
            float ov = __shfl_xor_sync(0xffffffffu, bv, off);
            int   oi = __shfl_xor_sync(0xffffffffu, bi, off);
            if (ov < bv || (ov == bv && oi < bi)) { bv = ov; bi = oi; }
        }
        if (l == bi) v = INFINITY;
        if (l == 0) {
            int j = g * NTOPK + r;
            int sl = bi / NTOPK, rr = bi - sl * NTOPK;
            int sf = g * NTOPK + sl;
            g_sflat[j] = sf;
            g_newsent[j] = g_sent[sf * NTOPK + rr];
            out_ev[j] = bv;
        }
    }
}

// ---------------- gathers ----------------
__global__ void k_gather(float* __restrict__ out_hidden)
{
    int j = blockIdx.x;
    int sf = g_sflat[j];
    for (int h = threadIdx.x; h < HDIM; h += blockDim.x) {
        float hv = g_hnew[sf * HDIM + h];
        out_hidden[(size_t)j * HDIM + h] = hv;
        g_cat[(size_t)j * 2 * HDIM + HDIM + h] = hv;
        g_cat[(size_t)j * 2 * HDIM + h] = g_ctx[(size_t)j * HDIM + h];
    }
}

__global__ void k_attnscores(const float* __restrict__ attn_in, float* __restrict__ out)
{
    int j = blockIdx.x, t = blockIdx.y;
    int sf = g_sflat[j];
    const float* src = (t < NSTEPS)
        ? (attn_in + ((size_t)t * NB + sf) * SDIM)
        : (g_attnout + (size_t)sf * SDIM);
    float* dst = out + ((size_t)t * NB + j) * SDIM;
    for (int s = threadIdx.x; s < SDIM; s += blockDim.x) dst[s] = src[s];
}

__global__ void k_mask_evidx(const float* __restrict__ mask_in,
                             const int* __restrict__ evidx_in,
                             float* __restrict__ out_mask,
                             float* __restrict__ out_evidx)
{
    int j = blockIdx.x;
    int sf = g_sflat[j];
    int sent = g_newsent[j];
    for (int s = threadIdx.x; s < SDIM; s += blockDim.x) {
        float v = mask_in[(size_t)sf * SDIM + s];
        if (s == sent) v = NEGV;
        out_mask[(size_t)j * SDIM + s] = v;
    }
    if (threadIdx.x < NTOPK) {
        int t = threadIdx.x;
        out_evidx[j * NTOPK + t] = (t < NSTEPS) ? (float)evidx_in[sf * NSTEPS + t]
                                                : (float)sent;
    }
}

// ---------------- launch ----------------
extern "C" void kernel_launch(void* const* d_in, const int* in_sizes, int n_in,
                              void* d_out, int out_size)
{
    const float* lasth  = (const float*)d_in[0];   // (1,160,1024)
    const float* dec    = (const float*)d_in[1];   // (160,1,1024)
    const float* enc    = (const float*)d_in[2];   // (160,512,1024)
    const float* attnsc = (const float*)d_in[3];   // (4,160,1,512)
    const float* maskin = (const float*)d_in[4];   // (160,1,512)
    const float* evsc   = (const float*)d_in[5];   // (160,)
    const int*   evidx  = (const int*)d_in[6];     // (160,4)
    const float* W1   = (const float*)d_in[7];
    const float* b1   = (const float*)d_in[8];
    const float* W2   = (const float*)d_in[9];
    const float* b2   = (const float*)d_in[10];
    const float* W3   = (const float*)d_in[11];
    const float* b3   = (const float*)d_in[12];
    const float* W_ih = (const float*)d_in[13];
    const float* W_hh = (const float*)d_in[14];
    const float* b_ih = (const float*)d_in[15];
    const float* b_hh = (const float*)d_in[16];

    float* out = (float*)d_out;
    float* o_result = out;                           // 160*1024
    float* o_hidden = out + 163840;                  // 160*1024
    float* o_evidx  = out + 327680;                  // 160*5
    float* o_attnsc = out + 328480;                  // 5*160*512
    float* o_mask   = out + 738080;                  // 160*512
    float* o_ev     = out + 820000;                  // 160

    // 1) GRU input/hidden GEMMs (fused over z)
    k_gru_gemm<<<dim3(24, 3, 2), 256>>>(dec, lasth, W_ih, W_hh, b_ih, b_hh);
    // 2) GRU gates -> h_new
    k_gates<<<NB, 256>>>(lasth);
    // 3) hb1 = h_new . b1
    k_hb1<<<NB, 256>>>(b1);
    // 4) q = h_new @ W1
    k_gemm_q<<<dim3(8, 3), 256>>>(W1);
    // 5) fused attention pass over enc (logits + online softmax + weighted sum)
    k_attn<<<dim3(NB, 2), 256>>>(enc, maskin);
    // 6) combine halves (normalizes c0 by Z)
    k_attn_combine<<<NB, 256>>>();
    // 7) per-row top-5
    k_topk<<<NB, 32>>>(evsc);
    // 8) beam selection (writes new_evidence_scores)
    k_beam<<<NBASE, 32>>>(o_ev);
    // 9) ctx = W2 @ c0[sflat] + b2  (gather in GEMM)
    k_gemm_ctx<<<dim3(8, 3), 256>>>(W2, b2);
    // 10) cat build + hidden gather
    k_gather<<<NB, 256>>>(o_hidden);
    // 11) result = cat @ W3^T + b3 -> d_out
    k_gemm_result<<<dim3(8, 3), 256>>>(W3, b3, o_result);
    // 12) attention scores stack gather
    k_attnscores<<<dim3(NB, NTOPK), 128>>>(attnsc, o_attnsc);
    // 13) mask scatter + evidence index gather
    k_mask_evidx<<<NB, 256>>>(maskin, evidx, o_mask, o_evidx);
    (void)in_sizes; (void)n_in; (void)out_size;
}

// round 3
// speedup vs baseline: 2.2757x; 2.2757x over previous
#include <cuda_runtime.h>
#include <math.h>
#include <stdint.h>

#define HDIM 1024
#define SDIM 512
#define NB   160
#define NTOPK 5
#define NSTEPS 4
#define NBASE 32
#define NEGV -10000000000.0f
#define NSPL 8          // K-splits for H=1024-ish GEMMs
#define NSPL_GRU 4      // K-splits per GRU gemm
#define NPART_ATTN 4    // attention s-splits per batch row

// ---------------- scratch (device globals) ----------------
__device__ __align__(16) float g_gip[NSPL_GRU * NB * 3 * HDIM];
__device__ __align__(16) float g_ghp[NSPL_GRU * NB * 3 * HDIM];
__device__ __align__(16) float g_qp [NSPL * NB * HDIM];
__device__ __align__(16) float g_ctxp[NSPL * NB * HDIM];
__device__ __align__(16) float g_resp[NSPL * NB * HDIM];
__device__ __align__(16) float g_hnew[NB * HDIM];
__device__ float g_hb1[NB];
__device__ __align__(16) float g_attnout[NB * SDIM];
__device__ float g_mpart[NB * NPART_ATTN];
__device__ float g_zpart[NB * NPART_ATTN];
__device__ __align__(16) float g_c0part[NB * NPART_ATTN * HDIM];
__device__ __align__(16) float g_c0[NB * HDIM];
__device__ float g_ls[NB * NTOPK];
__device__ int   g_sent[NB * NTOPK];
__device__ int   g_sflat[NB];
__device__ int   g_newsent[NB];
__device__ __align__(16) float g_cat[NB * 2 * HDIM];

// ---------------- f32x2 packed-FMA helpers ----------------
__device__ __forceinline__ unsigned long long f32x2_dup(float x) {
    unsigned long long r;
    asm("mov.b64 %0, {%1, %1};" : "=l"(r) : "f"(x));
    return r;
}
__device__ __forceinline__ void ffma2(unsigned long long& d, unsigned long long a, unsigned long long b) {
    asm("fma.rn.f32x2 %0, %1, %2, %0;" : "+l"(d) : "l"(a), "l"(b));
}
__device__ __forceinline__ float2 f32x2_unpack(unsigned long long v) {
    float2 r;
    asm("mov.b64 {%0, %1}, %2;" : "=f"(r.x), "=f"(r.y) : "l"(v));
    return r;
}

// ---------------- split-K fp32 GEMM tile, double-buffered ----------------
// Cpart[kz] += A[M, kchunk] * op(B);  partial stored (not atomic) at Cpart + kz*M*N.
// TRANSB=true : B is (N,K) row-major; false: B is (K,N) row-major.
// BM=64, BN=128, BK=16, 256 threads.
template <bool TRANSB>
__device__ __forceinline__ void gemm_splitk(
    const float* __restrict__ A, const float* __restrict__ B,
    float* __restrict__ Cpart,
    int M, int N, int K, int KCHUNK, const int* __restrict__ rowmap,
    int bx, int by, int kz)
{
    __shared__ __align__(16) float As[2][16][64];
    __shared__ __align__(16) float Bs[2][16][128];

    const int tid = threadIdx.x;
    const int tx = tid & 31;
    const int ty = tid >> 5;
    const int m0 = by * 64, n0 = bx * 128;
    const int kbase = kz * KCHUNK;

    unsigned long long acc[4][4];
#pragma unroll
    for (int i = 0; i < 4; i++)
#pragma unroll
        for (int j = 0; j < 4; j++) acc[i][j] = 0ull;

    // A load mapping
    const int am  = tid >> 2;
    const int akq = (tid & 3) * 4;
    const int arow = m0 + am;
    int arid = -1;
    if (arow < M) arid = rowmap ? rowmap[arow] : arow;

    // B load mapping (TRANSB)
    const int bn  = tid >> 1;
    const int bkq = (tid & 1) * 8;

    float4 a_reg;
    float4 b_reg0, b_reg1;

    auto ldg_tile = [&](int k0) {
        a_reg = make_float4(0.f, 0.f, 0.f, 0.f);
        if (arid >= 0)
            a_reg = *reinterpret_cast<const float4*>(A + (size_t)arid * K + k0 + akq);
        if (TRANSB) {
            const float* bp = B + (size_t)(n0 + bn) * K + k0 + bkq;
            b_reg0 = *reinterpret_cast<const float4*>(bp);
            b_reg1 = *reinterpret_cast<const float4*>(bp + 4);
        } else {
            int bk0 = tid >> 5, bnq0 = (tid & 31) * 4;
            int idx1 = tid + 256;
            int bk1 = idx1 >> 5, bnq1 = (idx1 & 31) * 4;
            b_reg0 = *reinterpret_cast<const float4*>(B + (size_t)(k0 + bk0) * N + n0 + bnq0);
            b_reg1 = *reinterpret_cast<const float4*>(B + (size_t)(k0 + bk1) * N + n0 + bnq1);
        }
    };
    auto sts_tile = [&](int buf) {
        As[buf][akq + 0][am] = a_reg.x; As[buf][akq + 1][am] = a_reg.y;
        As[buf][akq + 2][am] = a_reg.z; As[buf][akq + 3][am] = a_reg.w;
        if (TRANSB) {
            Bs[buf][bkq + 0][bn] = b_reg0.x; Bs[buf][bkq + 1][bn] = b_reg0.y;
            Bs[buf][bkq + 2][bn] = b_reg0.z; Bs[buf][bkq + 3][bn] = b_reg0.w;
            Bs[buf][bkq + 4][bn] = b_reg1.x; Bs[buf][bkq + 5][bn] = b_reg1.y;
            Bs[buf][bkq + 6][bn] = b_reg1.z; Bs[buf][bkq + 7][bn] = b_reg1.w;
        } else {
            int bk0 = tid >> 5, bnq0 = (tid & 31) * 4;
            int idx1 = tid + 256;
            int bk1 = idx1 >> 5, bnq1 = (idx1 & 31) * 4;
            *reinterpret_cast<float4*>(&Bs[buf][bk0][bnq0]) = b_reg0;
            *reinterpret_cast<float4*>(&Bs[buf][bk1][bnq1]) = b_reg1;
        }
    };

    const int nit = KCHUNK / 16;
    ldg_tile(kbase);
    sts_tile(0);
    __syncthreads();

    for (int i = 0; i < nit; i++) {
        const int cur = i & 1;
        if (i + 1 < nit) ldg_tile(kbase + 16 * (i + 1));   // LDG overlaps compute
#pragma unroll
        for (int k = 0; k < 16; k++) {
            const unsigned long long* Ar =
                reinterpret_cast<const unsigned long long*>(&As[cur][k][0]);
            unsigned long long a0 = Ar[ty * 4 + 0];
            unsigned long long a1 = Ar[ty * 4 + 1];
            unsigned long long a2 = Ar[ty * 4 + 2];
            unsigned long long a3 = Ar[ty * 4 + 3];
            float4 bv = *reinterpret_cast<const float4*>(&Bs[cur][k][tx * 4]);
            unsigned long long b0 = f32x2_dup(bv.x);
            unsigned long long b1 = f32x2_dup(bv.y);
            unsigned long long b2 = f32x2_dup(bv.z);
            unsigned long long b3 = f32x2_dup(bv.w);
            ffma2(acc[0][0], a0, b0); ffma2(acc[0][1], a0, b1);
            ffma2(acc[0][2], a0, b2); ffma2(acc[0][3], a0, b3);
            ffma2(acc[1][0], a1, b0); ffma2(acc[1][1], a1, b1);
            ffma2(acc[1][2], a1, b2); ffma2(acc[1][3], a1, b3);
            ffma2(acc[2][0], a2, b0); ffma2(acc[2][1], a2, b1);
            ffma2(acc[2][2], a2, b2); ffma2(acc[2][3], a2, b3);
            ffma2(acc[3][0], a3, b0); ffma2(acc[3][1], a3, b1);
            ffma2(acc[3][2], a3, b2); ffma2(acc[3][3], a3, b3);
        }
        if (i + 1 < nit) sts_tile((i + 1) & 1);
        __syncthreads();
    }

    float* Cp = Cpart + (size_t)kz * M * N;
    const int cbase = n0 + tx * 4;
#pragma unroll
    for (int ii = 0; ii < 4; ii++) {
        float2 u0 = f32x2_unpack(acc[ii][0]);
        float2 u1 = f32x2_unpack(acc[ii][1]);
        float2 u2 = f32x2_unpack(acc[ii][2]);
        float2 u3 = f32x2_unpack(acc[ii][3]);
        int r0 = m0 + ty * 8 + ii * 2;
        if (r0 < M)
            *reinterpret_cast<float4*>(&Cp[(size_t)r0 * N + cbase]) =
                make_float4(u0.x, u1.x, u2.x, u3.x);
        if (r0 + 1 < M)
            *reinterpret_cast<float4*>(&Cp[(size_t)(r0 + 1) * N + cbase]) =
                make_float4(u0.y, u1.y, u2.y, u3.y);
    }
}

// ---------------- GEMM wrappers ----------------
__global__ void k_gru_gemm(const float* __restrict__ dec, const float* __restrict__ lasth,
                           const float* __restrict__ W_ih, const float* __restrict__ W_hh)
{
    int which = blockIdx.z >> 2;        // 0 = gi, 1 = gh
    int kz = blockIdx.z & 3;
    const float* A = which ? lasth : dec;
    const float* B = which ? W_hh : W_ih;
    float* C       = which ? g_ghp : g_gip;
    gemm_splitk<true>(A, B, C, NB, 3 * HDIM, HDIM, HDIM / NSPL_GRU, nullptr,
                      blockIdx.x, blockIdx.y, kz);
}

__global__ void k_gemm_q(const float* __restrict__ W1)
{
    gemm_splitk<false>(g_hnew, W1, g_qp, NB, HDIM, HDIM, HDIM / NSPL, nullptr,
                       blockIdx.x, blockIdx.y, blockIdx.z);
}

__global__ void k_gemm_ctx(const float* __restrict__ W2)
{
    gemm_splitk<true>(g_c0, W2, g_ctxp, NB, HDIM, HDIM, HDIM / NSPL, g_sflat,
                      blockIdx.x, blockIdx.y, blockIdx.z);
}

__global__ void k_gemm_result(const float* __restrict__ W3)
{
    gemm_splitk<true>(g_cat, W3, g_resp, NB, HDIM, 2 * HDIM, 2 * HDIM / NSPL, nullptr,
                      blockIdx.x, blockIdx.y, blockIdx.z);
}

// ---------------- GRU gates: reduce split-K partials + gates + hb1 ----------------
__global__ void k_gates(const float* __restrict__ lasth,
                        const float* __restrict__ b_ih, const float* __restrict__ b_hh,
                        const float* __restrict__ b1)
{
    const int b = blockIdx.x;
    const int t = threadIdx.x;          // 0..255, each handles 4 consecutive n
    const int n = t * 4;

    float4 gir = *reinterpret_cast<const float4*>(b_ih + n);
    float4 giz = *reinterpret_cast<const float4*>(b_ih + HDIM + n);
    float4 gin = *reinterpret_cast<const float4*>(b_ih + 2 * HDIM + n);
    float4 ghr = *reinterpret_cast<const float4*>(b_hh + n);
    float4 ghz = *reinterpret_cast<const float4*>(b_hh + HDIM + n);
    float4 ghn = *reinterpret_cast<const float4*>(b_hh + 2 * HDIM + n);

#pragma unroll
    for (int s = 0; s < NSPL_GRU; s++) {
        const float* gi = g_gip + ((size_t)s * NB + b) * 3 * HDIM;
        const float* gh = g_ghp + ((size_t)s * NB + b) * 3 * HDIM;
        float4 v;
        v = *reinterpret_cast<const float4*>(gi + n);            gir.x += v.x; gir.y += v.y; gir.z += v.z; gir.w += v.w;
        v = *reinterpret_cast<const float4*>(gi + HDIM + n);     giz.x += v.x; giz.y += v.y; giz.z += v.z; giz.w += v.w;
        v = *reinterpret_cast<const float4*>(gi + 2 * HDIM + n); gin.x += v.x; gin.y += v.y; gin.z += v.z; gin.w += v.w;
        v = *reinterpret_cast<const float4*>(gh + n);            ghr.x += v.x; ghr.y += v.y; ghr.z += v.z; ghr.w += v.w;
        v = *reinterpret_cast<const float4*>(gh + HDIM + n);     ghz.x += v.x; ghz.y += v.y; ghz.z += v.z; ghz.w += v.w;
        v = *reinterpret_cast<const float4*>(gh + 2 * HDIM + n); ghn.x += v.x; ghn.y += v.y; ghn.z += v.z; ghn.w += v.w;
    }

    float4 hp = *reinterpret_cast<const float4*>(lasth + (size_t)b * HDIM + n);
    float4 b1v = *reinterpret_cast<const float4*>(b1 + n);
    float4 hn;
    float dot = 0.f;
    {
        float r, z, nn;
        r = 1.f / (1.f + __expf(-(gir.x + ghr.x)));
        z = 1.f / (1.f + __expf(-(giz.x + ghz.x)));
        nn = tanhf(gin.x + r * ghn.x);
        hn.x = (1.f - z) * nn + z * hp.x;
        r = 1.f / (1.f + __expf(-(gir.y + ghr.y)));
        z = 1.f / (1.f + __expf(-(giz.y + ghz.y)));
        nn = tanhf(gin.y + r * ghn.y);
        hn.y = (1.f - z) * nn + z * hp.y;
        r = 1.f / (1.f + __expf(-(gir.z + ghr.z)));
        z = 1.f / (1.f + __expf(-(giz.z + ghz.z)));
        nn = tanhf(gin.z + r * ghn.z);
        hn.z = (1.f - z) * nn + z * hp.z;
        r = 1.f / (1.f + __expf(-(gir.w + ghr.w)));
        z = 1.f / (1.f + __expf(-(giz.w + ghz.w)));
        nn = tanhf(gin.w + r * ghn.w);
        hn.w = (1.f - z) * nn + z * hp.w;
        dot = hn.x * b1v.x + hn.y * b1v.y + hn.z * b1v.z + hn.w * b1v.w;
    }
    *reinterpret_cast<float4*>(g_hnew + (size_t)b * HDIM + n) = hn;

    // block-reduce dot -> g_hb1[b]
    __shared__ float red[256];
    red[t] = dot;
    __syncthreads();
    for (int off = 128; off > 0; off >>= 1) {
        if (t < off) red[t] += red[t + off];
        __syncthreads();
    }
    if (t == 0) g_hb1[b] = red[0];
}

// ---------------- fused attention pass ----------------
// grid (160, 4), 256 threads; each warp handles 16 s-rows. Reduces q split-K partials inline.
__global__ void __launch_bounds__(256, 2) k_attn(const float* __restrict__ enc,
                                                 const float* __restrict__ mask)
{
    const int b = blockIdx.x;
    const int part = blockIdx.y;
    const int w = threadIdx.x >> 5, l = threadIdx.x & 31;

    // q row = sum of NSPL split-K partials
    float4 qr[8];
#pragma unroll
    for (int j = 0; j < 8; j++) qr[j] = make_float4(0.f, 0.f, 0.f, 0.f);
#pragma unroll
    for (int s = 0; s < NSPL; s++) {
        const float4* qp = reinterpret_cast<const float4*>(
            g_qp + ((size_t)s * NB + b) * HDIM);
#pragma unroll
        for (int j = 0; j < 8; j++) {
            float4 v = qp[l + 32 * j];
            qr[j].x += v.x; qr[j].y += v.y; qr[j].z += v.z; qr[j].w += v.w;
        }
    }
    const float hb1 = g_hb1[b];

    float4 acc[8];
#pragma unroll
    for (int j = 0; j < 8; j++) acc[j] = make_float4(0.f, 0.f, 0.f, 0.f);
    float m = -INFINITY, Z = 0.f;
    float mylogit = 0.f;

    const float4* encb = reinterpret_cast<const float4*>(enc + (size_t)b * SDIM * HDIM);
    const int srow0 = part * 128 + w * 16;

    for (int t = 0; t < 16; t++) {
        const int s = srow0 + t;
        const float4* rp = encb + (size_t)s * (HDIM / 4);
        float4 e[8];
        float d = 0.f;
#pragma unroll
        for (int j = 0; j < 8; j++) {
            e[j] = rp[l + 32 * j];
            d += e[j].x * qr[j].x + e[j].y * qr[j].y + e[j].z * qr[j].z + e[j].w * qr[j].w;
        }
#pragma unroll
        for (int off = 16; off; off >>= 1) d += __shfl_xor_sync(0xffffffffu, d, off);

        float logit = (d + hb1) * 0.03125f + mask[b * SDIM + s];
        if (t == l) mylogit = logit;

        float mn = fmaxf(m, logit);
        float corr = __expf(m - mn);
        float p = __expf(logit - mn);
        Z = Z * corr + p;
#pragma unroll
        for (int j = 0; j < 8; j++) {
            acc[j].x = acc[j].x * corr + p * e[j].x;
            acc[j].y = acc[j].y * corr + p * e[j].y;
            acc[j].z = acc[j].z * corr + p * e[j].z;
            acc[j].w = acc[j].w * corr + p * e[j].w;
        }
        m = mn;
    }
    if (l < 16) g_attnout[b * SDIM + srow0 + l] = mylogit;

    __shared__ float sm[8], sz[8];
    __shared__ __align__(16) float c0s[8][HDIM];
    if (l == 0) sm[w] = m;
    __syncthreads();
    float M2 = sm[0];
#pragma unroll
    for (int i = 1; i < 8; i++) M2 = fmaxf(M2, sm[i]);
    float f = __expf(m - M2);
    float4* crow = reinterpret_cast<float4*>(&c0s[w][0]);
#pragma unroll
    for (int j = 0; j < 8; j++) {
        float4 v = acc[j];
        v.x *= f; v.y *= f; v.z *= f; v.w *= f;
        crow[l + 32 * j] = v;
    }
    if (l == 0) sz[w] = Z * f;
    __syncthreads();

    float Ztot = 0.f;
#pragma unroll
    for (int i = 0; i < 8; i++) Ztot += sz[i];
    for (int h = threadIdx.x; h < HDIM; h += 256) {
        float ssum = 0.f;
#pragma unroll
        for (int wi = 0; wi < 8; wi++) ssum += c0s[wi][h];
        g_c0part[((size_t)b * NPART_ATTN + part) * HDIM + h] = ssum;
    }
    if (threadIdx.x == 0) {
        g_mpart[b * NPART_ATTN + part] = M2;
        g_zpart[b * NPART_ATTN + part] = Ztot;
    }
}

// ---------------- combine parts + per-row top-5 (fused) ----------------
__global__ void k_combine_topk(const float* __restrict__ ev)
{
    const int b = blockIdx.x;
    float mv[NPART_ATTN], zv[NPART_ATTN];
#pragma unroll
    for (int i = 0; i < NPART_ATTN; i++) {
        mv[i] = g_mpart[b * NPART_ATTN + i];
        zv[i] = g_zpart[b * NPART_ATTN + i];
    }
    float M2 = mv[0];
#pragma unroll
    for (int i = 1; i < NPART_ATTN; i++) M2 = fmaxf(M2, mv[i]);
    float fct[NPART_ATTN];
    float Zt = 0.f;
#pragma unroll
    for (int i = 0; i < NPART_ATTN; i++) { fct[i] = __expf(mv[i] - M2); Zt += zv[i] * fct[i]; }
    const float inv = 1.0f / Zt;

    for (int h = threadIdx.x; h < HDIM; h += 256) {
        float ssum = 0.f;
#pragma unroll
        for (int i = 0; i < NPART_ATTN; i++)
            ssum += g_c0part[((size_t)b * NPART_ATTN + i) * HDIM + h] * fct[i];
        g_c0[b * HDIM + h] = ssum * inv;
    }

    // warp 0: top-5 of attnout row (max val, min index tie-break)
    if (threadIdx.x < 32) {
        const int l = threadIdx.x;
        float vals[16];
#pragma unroll
        for (int j = 0; j < 16; j++) vals[j] = g_attnout[b * SDIM + l + 32 * j];
        const float lse = M2 + logf(Zt);
        const float evb = ev[b];
        for (int r = 0; r < NTOPK; r++) {
            float bv = -INFINITY; int bj = 0;
#pragma unroll
            for (int j = 0; j < 16; j++)
                if (vals[j] > bv) { bv = vals[j]; bj = j; }
            int bi = l + 32 * bj;
            if (bv == -INFINITY) bi = 0x7fffffff;
#pragma unroll
            for (int off = 16; off; off >>= 1) {
                float ov = __shfl_xor_sync(0xffffffffu, bv, off);
                int   oi = __shfl_xor_sync(0xffffffffu, bi, off);
                if (ov > bv || (ov == bv && oi < bi)) { bv = ov; bi = oi; }
            }
            if ((bi & 31) == l && (bi >> 5) < 16) vals[bi >> 5] = -INFINITY;
            if (l == 0) {
                g_ls[b * NTOPK + r] = lse - bv + evb;
                g_sent[b * NTOPK + r] = bi;
            }
        }
    }
}

// ---------------- beam select: 5 smallest of 25, stable ----------------
__global__ void k_beam(float* __restrict__ out_ev)
{
    int g = blockIdx.x, l = threadIdx.x;
    float v = (l < 25) ? g_ls[g * 25 + l] : INFINITY;
    for (int r = 0; r < NTOPK; r++) {
        float bv = v; int bi = l;
#pragma unroll
        for (int off = 16; off; off >>= 1) {
            float ov = __shfl_xor_sync(0xffffffffu, bv, off);
            int   oi = __shfl_xor_sync(0xffffffffu, bi, off);
            if (ov < bv || (ov == bv && oi < bi)) { bv = ov; bi = oi; }
        }
        if (l == bi) v = INFINITY;
        if (l == 0) {
            int j = g * NTOPK + r;
            int sl = bi / NTOPK, rr = bi - sl * NTOPK;
            int sf = g * NTOPK + sl;
            g_sflat[j] = sf;
            g_newsent[j] = g_sent[sf * NTOPK + rr];
            out_ev[j] = bv;
        }
    }
}

// ---------------- outputs: attn score stack + mask + evidx (fused) ----------------
__global__ void k_outputs(const float* __restrict__ attn_in,
                          const float* __restrict__ mask_in,
                          const int* __restrict__ evidx_in,
                          float* __restrict__ out_attnsc,
                          float* __restrict__ out_mask,
                          float* __restrict__ out_evidx)
{
    const int j = blockIdx.x, t = blockIdx.y;
    const int sf = g_sflat[j];
    if (t < 5) {
        const float4* src = reinterpret_cast<const float4*>(
            (t < NSTEPS) ? (attn_in + ((size_t)t * NB + sf) * SDIM)
                         : (g_attnout + (size_t)sf * SDIM));
        float4* dst = reinterpret_cast<float4*>(out_attnsc + ((size_t)t * NB + j) * SDIM);
        dst[threadIdx.x] = src[threadIdx.x];
    } else {
        const int sent = g_newsent[j];
        for (int s = threadIdx.x; s < SDIM; s += 128) {
            float v = mask_in[(size_t)sf * SDIM + s];
            if (s == sent) v = NEGV;
            out_mask[(size_t)j * SDIM + s] = v;
        }
        if (threadIdx.x < NTOPK)
            out_evidx[j * NTOPK + threadIdx.x] =
                (threadIdx.x < NSTEPS) ? (float)evidx_in[sf * NSTEPS + threadIdx.x]
                                       : (float)sent;
    }
}

// ---------------- gather: reduce ctx partials + b2, build cat, emit hidden ----------------
__global__ void k_gather(const float* __restrict__ b2, float* __restrict__ out_hidden)
{
    const int j = blockIdx.x;
    const int sf = g_sflat[j];
    const int n = threadIdx.x * 4;

    float4 c = *reinterpret_cast<const float4*>(b2 + n);
#pragma unroll
    for (int s = 0; s < NSPL; s++) {
        float4 v = *reinterpret_cast<const float4*>(
            g_ctxp + ((size_t)s * NB + j) * HDIM + n);
        c.x += v.x; c.y += v.y; c.z += v.z; c.w += v.w;
    }
    float4 hv = *reinterpret_cast<const float4*>(g_hnew + (size_t)sf * HDIM + n);

    *reinterpret_cast<float4*>(g_cat + (size_t)j * 2 * HDIM + n) = c;
    *reinterpret_cast<float4*>(g_cat + (size_t)j * 2 * HDIM + HDIM + n) = hv;
    *reinterpret_cast<float4*>(out_hidden + (size_t)j * HDIM + n) = hv;
}

// ---------------- result reduce: sum partials + b3 -> d_out ----------------
__global__ void k_res_reduce(const float* __restrict__ b3, float* __restrict__ out_result)
{
    const int j = blockIdx.x;
    const int n = threadIdx.x * 4;
    float4 r = *reinterpret_cast<const float4*>(b3 + n);
#pragma unroll
    for (int s = 0; s < NSPL; s++) {
        float4 v = *reinterpret_cast<const float4*>(
            g_resp + ((size_t)s * NB + j) * HDIM + n);
        r.x += v.x; r.y += v.y; r.z += v.z; r.w += v.w;
    }
    *reinterpret_cast<float4*>(out_result + (size_t)j * HDIM + n) = r;
}

// ---------------- launch ----------------
extern "C" void kernel_launch(void* const* d_in, const int* in_sizes, int n_in,
                              void* d_out, int out_size)
{
    const float* lasth  = (const float*)d_in[0];
    const float* dec    = (const float*)d_in[1];
    const float* enc    = (const float*)d_in[2];
    const float* attnsc = (const float*)d_in[3];
    const float* maskin = (const float*)d_in[4];
    const float* evsc   = (const float*)d_in[5];
    const int*   evidx  = (const int*)d_in[6];
    const float* W1   = (const float*)d_in[7];
    const float* b1   = (const float*)d_in[8];
    const float* W2   = (const float*)d_in[9];
    const float* b2   = (const float*)d_in[10];
    const float* W3   = (const float*)d_in[11];
    const float* b3   = (const float*)d_in[12];
    const float* W_ih = (const float*)d_in[13];
    const float* W_hh = (const float*)d_in[14];
    const float* b_ih = (const float*)d_in[15];
    const float* b_hh = (const float*)d_in[16];

    float* out = (float*)d_out;
    float* o_result = out;              // 160*1024
    float* o_hidden = out + 163840;     // 160*1024
    float* o_evidx  = out + 327680;     // 160*5
    float* o_attnsc = out + 328480;     // 5*160*512
    float* o_mask   = out + 738080;     // 160*512
    float* o_ev     = out + 820000;     // 160

    // 1) GRU GEMMs, split-K (2 gemms x 4 splits = 576 blocks)
    k_gru_gemm<<<dim3(24, 3, 8), 256>>>(dec, lasth, W_ih, W_hh);
    // 2) gates + hb1 (reduces partials)
    k_gates<<<NB, 256>>>(lasth, b_ih, b_hh, b1);
    // 3) q = h_new @ W1, split-K (192 blocks)
    k_gemm_q<<<dim3(8, 3, NSPL), 256>>>(W1);
    // 4) fused attention (640 blocks; reduces q partials)
    k_attn<<<dim3(NB, NPART_ATTN), 256>>>(enc, maskin);
    // 5) combine + topk
    k_combine_topk<<<NB, 256>>>(evsc);
    // 6) beam select
    k_beam<<<NBASE, 32>>>(o_ev);
    // 7) output gathers (scores/mask/evidx)
    k_outputs<<<dim3(NB, 6), 128>>>(attnsc, maskin, evidx, o_attnsc, o_mask, o_evidx);
    // 8) ctx = W2 @ c0[sflat], split-K
    k_gemm_ctx<<<dim3(8, 3, NSPL), 256>>>(W2);
    // 9) gather: reduce ctx + b2, build cat, emit hidden
    k_gather<<<NB, 256>>>(b2, o_hidden);
    // 10) result GEMM, split-K
    k_gemm_result<<<dim3(8, 3, NSPL), 256>>>(W3);
    // 11) reduce result partials + b3 -> out
    k_res_reduce<<<NB, 256>>>(b3, o_result);
    (void)in_sizes; (void)n_in; (void)out_size;
}